// round 7
// baseline (speedup 1.0000x reference)
#include <cuda_runtime.h>
#include <cstdint>

// Problem constants
#define BATCH   32768
#define F_IN    64
#define HID     32
#define EMO     25
#define NHG     96          // H*G = 8*12
#define EP      28          // EMO padded to float4 multiple
#define BN_EPS  1e-5f
#define L1_EPS  1e-12f
#define WB_TOT  (4 * HID * EMO + 4 * EMO)   // 3300 weights+biases per 4-hg group
#define PREF_N  13                           // ceil(3300/256)

// Scratch (static device allocations are allowed)
__device__ float g_h2[BATCH * HID];      // pre-BN second-layer activations, 4 MB
__device__ float g_part[128 * 64];       // per-block partial [sum(32), sumsq(32)]
__device__ float g_bn[64];               // [scale(32), bias(32)] folded BN params

__device__ __forceinline__ float selu_f(float x) {
    const float LAM = 1.0507009873554805f;
    const float AL  = 1.6732632423543772f;
    return x > 0.f ? LAM * x : LAM * AL * (__expf(x) - 1.f);
}

// ---- packed fp32x2 helpers (FFMA2: 2 fp32 FMAs per instruction on sm_103a) ----
__device__ __forceinline__ unsigned long long pack2(float lo, float hi) {
    unsigned long long r;
    asm("mov.b64 %0, {%1, %2};" : "=l"(r) : "f"(lo), "f"(hi));
    return r;
}
__device__ __forceinline__ void unpack2(unsigned long long v, float& lo, float& hi) {
    asm("mov.b64 {%0, %1}, %2;" : "=f"(lo), "=f"(hi) : "l"(v));
}
__device__ __forceinline__ void fma2(unsigned long long& d,
                                     unsigned long long a, unsigned long long b) {
    asm("fma.rn.f32x2 %0, %1, %2, %3;" : "=l"(d) : "l"(a), "l"(b), "l"(d));
}

// ---------------------------------------------------------------------------
// Kernel 1: h2 = selu(X@W1+b1)@W2 + b2      (one thread per batch row)
// ---------------------------------------------------------------------------
__global__ void __launch_bounds__(256) k_feat(
    const float* __restrict__ X,  const float* __restrict__ W1,
    const float* __restrict__ b1, const float* __restrict__ W2,
    const float* __restrict__ b2)
{
    __shared__ __align__(16) float w1s[F_IN * HID];   // 2048
    __shared__ __align__(16) float w2s[HID * HID];    // 1024
    __shared__ __align__(16) float b1s[HID];
    __shared__ __align__(16) float b2s[HID];

    int tid = threadIdx.x;
    for (int i = tid; i < F_IN * HID; i += 256) w1s[i] = W1[i];
    for (int i = tid; i < HID * HID; i += 256) w2s[i] = W2[i];
    if (tid < HID) { b1s[tid] = b1[tid]; b2s[tid] = b2[tid]; }
    __syncthreads();

    int row = blockIdx.x * 256 + tid;
    const float4* xg = reinterpret_cast<const float4*>(X + (size_t)row * F_IN);

    float4 h[8];
    const float4* b1v = reinterpret_cast<const float4*>(b1s);
#pragma unroll
    for (int j = 0; j < 8; j++) h[j] = b1v[j];

    const float4* w1v = reinterpret_cast<const float4*>(w1s);
#pragma unroll 4
    for (int i = 0; i < 16; i++) {
        float4 xv = xg[i];
#pragma unroll
        for (int c = 0; c < 4; c++) {
            float xi = (c == 0) ? xv.x : (c == 1) ? xv.y : (c == 2) ? xv.z : xv.w;
            int ii = i * 4 + c;
#pragma unroll
            for (int j = 0; j < 8; j++) {
                float4 w = w1v[ii * 8 + j];
                h[j].x = fmaf(xi, w.x, h[j].x);
                h[j].y = fmaf(xi, w.y, h[j].y);
                h[j].z = fmaf(xi, w.z, h[j].z);
                h[j].w = fmaf(xi, w.w, h[j].w);
            }
        }
    }
#pragma unroll
    for (int j = 0; j < 8; j++) {
        h[j].x = selu_f(h[j].x); h[j].y = selu_f(h[j].y);
        h[j].z = selu_f(h[j].z); h[j].w = selu_f(h[j].w);
    }

    float4 o[8];
    const float4* b2v = reinterpret_cast<const float4*>(b2s);
#pragma unroll
    for (int j = 0; j < 8; j++) o[j] = b2v[j];

    const float4* w2v = reinterpret_cast<const float4*>(w2s);
#pragma unroll
    for (int i = 0; i < 8; i++) {
#pragma unroll
        for (int c = 0; c < 4; c++) {
            float hi = (c == 0) ? h[i].x : (c == 1) ? h[i].y : (c == 2) ? h[i].z : h[i].w;
            int ii = i * 4 + c;
#pragma unroll
            for (int j = 0; j < 8; j++) {
                float4 w = w2v[ii * 8 + j];
                o[j].x = fmaf(hi, w.x, o[j].x);
                o[j].y = fmaf(hi, w.y, o[j].y);
                o[j].z = fmaf(hi, w.z, o[j].z);
                o[j].w = fmaf(hi, w.w, o[j].w);
            }
        }
    }
    float4* og = reinterpret_cast<float4*>(g_h2 + (size_t)row * HID);
#pragma unroll
    for (int j = 0; j < 8; j++) og[j] = o[j];
}

// ---------------------------------------------------------------------------
// Kernel 2: deterministic per-block partial sums of h2 and h2^2 per column
// ---------------------------------------------------------------------------
__global__ void __launch_bounds__(256) k_stats()
{
    __shared__ float ss1[256];
    __shared__ float ss2[256];
    int tid = threadIdx.x;
    int col = tid & 31;
    int grp = tid >> 5;               // 0..7
    int base = blockIdx.x * 256;      // 256 rows per block, 128 blocks

    float s1 = 0.f, s2 = 0.f;
    for (int r = grp; r < 256; r += 8) {
        float v = g_h2[(size_t)(base + r) * HID + col];
        s1 += v; s2 += v * v;
    }
    ss1[tid] = s1; ss2[tid] = s2;
    __syncthreads();
    if (tid < 32) {
        float a = 0.f, b = 0.f;
#pragma unroll
        for (int g = 0; g < 8; g++) { a += ss1[g * 32 + tid]; b += ss2[g * 32 + tid]; }
        g_part[blockIdx.x * 64 + tid]      = a;
        g_part[blockIdx.x * 64 + 32 + tid] = b;
    }
}

// ---------------------------------------------------------------------------
// Kernel 3: finalize BN params  (scale = gamma*rstd, bias = beta - mu*scale)
// ---------------------------------------------------------------------------
__global__ void k_bn(const float* __restrict__ gamma, const float* __restrict__ beta)
{
    __shared__ float tot[64];
    int tid = threadIdx.x;   // 64 threads
    float a = 0.f;
    for (int b = 0; b < 128; b++) a += g_part[b * 64 + tid];
    tot[tid] = a;
    __syncthreads();
    if (tid < 32) {
        float S = tot[tid], Q = tot[tid + 32];
        float mu  = S * (1.f / BATCH);
        float var = Q * (1.f / BATCH) - mu * mu;
        float rstd = rsqrtf(var + BN_EPS);
        float sc = gamma[tid] * rstd;
        g_bn[tid]      = sc;
        g_bn[32 + tid] = beta[tid] - mu * sc;
    }
}

// ---------------------------------------------------------------------------
// Kernel 4: e = selu(BN(h2)); d = selu(e @ Wh + bh); out = d / max(sum|d|,eps)
// Block: 128 batch rows x all 96 hg groups (4 at a time).
// Thread: (hgLocal = tid>>6) x 2 rows (rl, rl+64), 25 outputs each.
// Packed fp32x2 FFMA2 inner product; register prefetch of next group's
// weights; double-buffered store staging (stageB overlays the dead ws tile).
// Pad lanes 25..27 of each accumulator pair are never read, so ws/bhs pad
// columns are left uninitialized (lane-wise packed math cannot leak across).
// ---------------------------------------------------------------------------
__global__ void __launch_bounds__(256, 2) k_heads(
    const float* __restrict__ Wh, const float* __restrict__ bh,
    float* __restrict__ out)
{
    __shared__ float es[128 * 33];                  // e tile, padded stride 33
    __shared__ __align__(16) char ws_raw[4 * HID * EP * 4];  // ws | stageB overlay
    __shared__ __align__(16) float bhs[4][EP];
    __shared__ float bns[64];
    __shared__ float stageA[128 * EMO];             // store-coalescing staging

    float (*ws)[HID][EP] = reinterpret_cast<float (*)[HID][EP]>(ws_raw);
    float* stageB = reinterpret_cast<float*>(ws_raw);   // 12800 floats fit in 14336

    int tid = threadIdx.x;

    // prologue: prefetch group 0's weights+biases (overlaps es fill below)
    float pref[PREF_N];
#pragma unroll
    for (int j = 0; j < PREF_N; j++) {
        int idx = tid + j * 256;
        if (idx < WB_TOT)
            pref[j] = (idx < 4 * HID * EMO) ? Wh[idx] : bh[idx - 4 * HID * EMO];
    }

    if (tid < 64) bns[tid] = g_bn[tid];
    if (tid < 4 * (EP - EMO)) bhs[tid / (EP - EMO)][EMO + tid % (EP - EMO)] = 0.f;
    __syncthreads();   // bns visible for es fill

    int rowBase = blockIdx.x * 128;
    {   // fill es with BN + selu applied
        const float4* src = reinterpret_cast<const float4*>(g_h2 + (size_t)rowBase * HID);
        for (int i = tid; i < 1024; i += 256) {
            float4 v = src[i];
            int row = i >> 3;
            int c   = (i & 7) * 4;
            es[row * 33 + c + 0] = selu_f(fmaf(v.x, bns[c + 0], bns[32 + c + 0]));
            es[row * 33 + c + 1] = selu_f(fmaf(v.y, bns[c + 1], bns[32 + c + 1]));
            es[row * 33 + c + 2] = selu_f(fmaf(v.z, bns[c + 2], bns[32 + c + 2]));
            es[row * 33 + c + 3] = selu_f(fmaf(v.w, bns[c + 3], bns[32 + c + 3]));
        }
    }
    __syncthreads();

    const int hgL = tid >> 6;   // 0..3, warp-uniform
    const int rl  = tid & 63;   // rows rl and rl+64

    for (int grp = 0; grp < 24; grp++) {
        // stage prefetched weights into smem (ws region free: prev iter's final
        // stageB reads were ordered by the trailing __syncthreads()).
#pragma unroll
        for (int j = 0; j < PREF_N; j++) {
            int idx = tid + j * 256;
            if (idx < 4 * HID * EMO) {
                int hgl = idx / (HID * EMO);
                int rem = idx % (HID * EMO);
                ws[hgl][rem / EMO][rem % EMO] = pref[j];
            } else if (idx < WB_TOT) {
                int r2 = idx - 4 * HID * EMO;
                bhs[r2 / EMO][r2 % EMO] = pref[j];
            }
        }
        __syncthreads();

        // prefetch next group's weights (latency hidden under compute below)
        if (grp + 1 < 24) {
            const float* wsrc = Wh + (size_t)(grp + 1) * 4 * HID * EMO;
            const float* bsrc = bh + (size_t)(grp + 1) * 4 * EMO;
#pragma unroll
            for (int j = 0; j < PREF_N; j++) {
                int idx = tid + j * 256;
                if (idx < WB_TOT)
                    pref[j] = (idx < 4 * HID * EMO) ? wsrc[idx]
                                                    : bsrc[idx - 4 * HID * EMO];
            }
        }

        // 14 packed accumulators per row (28 fp32 lanes; lanes 25..27 dead)
        unsigned long long A0[EP / 2], A1[EP / 2];
        const unsigned long long* bhp =
            reinterpret_cast<const unsigned long long*>(&bhs[hgL][0]);
#pragma unroll
        for (int j = 0; j < EP / 2; j++) { A0[j] = bhp[j]; A1[j] = bhp[j]; }

#pragma unroll 4
        for (int k = 0; k < HID; k++) {
            unsigned long long E0 = pack2(es[rl * 33 + k],        es[rl * 33 + k]);
            unsigned long long E1 = pack2(es[(rl + 64) * 33 + k], es[(rl + 64) * 33 + k]);
            const unsigned long long* wp =
                reinterpret_cast<const unsigned long long*>(&ws[hgL][k][0]);
#pragma unroll
            for (int j = 0; j < EP / 2; j++) {
                unsigned long long w2 = wp[j];
                fma2(A0[j], E0, w2);
                fma2(A1[j], E1, w2);
            }
        }

        float a0[EP], a1[EP];
#pragma unroll
        for (int j = 0; j < EP / 2; j++) {
            unpack2(A0[j], a0[2 * j], a0[2 * j + 1]);
            unpack2(A1[j], a1[2 * j], a1[2 * j + 1]);
        }

        // selu + L1 normalization factors (lanes >= EMO ignored)
        float s0 = 0.f, s1 = 0.f;
#pragma unroll
        for (int e = 0; e < EMO; e++) {
            a0[e] = selu_f(a0[e]); s0 += fabsf(a0[e]);
            a1[e] = selu_f(a1[e]); s1 += fabsf(a1[e]);
        }
        float inv0 = 1.f / fmaxf(s0, L1_EPS);
        float inv1 = 1.f / fmaxf(s1, L1_EPS);

        // pipelined staged stores: stage s in {A,B} alternating; the write of
        // stage s+1 overlaps the store of stage s. (ws is dead here; its
        // region is stageB. All cross-buffer hazards barrier-ordered.)
        if (hgL == 0) {
#pragma unroll
            for (int e = 0; e < EMO; e++) {
                stageA[rl * EMO + e]        = a0[e] * inv0;
                stageA[(rl + 64) * EMO + e] = a1[e] * inv1;
            }
        }
        __syncthreads();
#pragma unroll
        for (int s = 0; s < 4; s++) {
            float* cur = (s & 1) ? stageB : stageA;
            float* nxt = (s & 1) ? stageA : stageB;
            if (s + 1 < 4 && hgL == s + 1) {
#pragma unroll
                for (int e = 0; e < EMO; e++) {
                    nxt[rl * EMO + e]        = a0[e] * inv0;
                    nxt[(rl + 64) * EMO + e] = a1[e] * inv1;
                }
            }
            {
                int lane = tid & 31;
                int hg = grp * 4 + s;
                float* ob = out + (size_t)rowBase * (NHG * EMO) + (size_t)hg * EMO;
                if (lane < EMO) {
                    for (int rr = tid >> 5; rr < 128; rr += 8)
                        __stcs(&ob[(size_t)rr * (NHG * EMO) + lane],
                               cur[rr * EMO + lane]);
                }
            }
            __syncthreads();
        }
    }
}

// ---------------------------------------------------------------------------
extern "C" void kernel_launch(void* const* d_in, const int* in_sizes, int n_in,
                              void* d_out, int out_size)
{
    const float* X     = (const float*)d_in[0];
    const float* W1    = (const float*)d_in[1];
    const float* b1    = (const float*)d_in[2];
    const float* W2    = (const float*)d_in[3];
    const float* b2    = (const float*)d_in[4];
    const float* gamma = (const float*)d_in[5];
    const float* beta  = (const float*)d_in[6];
    const float* Wh    = (const float*)d_in[7];
    const float* bh    = (const float*)d_in[8];
    float* out = (float*)d_out;

    k_feat <<<BATCH / 256, 256>>>(X, W1, b1, W2, b2);
    k_stats<<<128, 256>>>();
    k_bn   <<<1, 64>>>(gamma, beta);
    k_heads<<<BATCH / 128, 256>>>(Wh, bh, out);
}

// round 10
// speedup vs baseline: 1.0984x; 1.0984x over previous
#include <cuda_runtime.h>
#include <cstdint>

// Problem constants
#define BATCH   32768
#define F_IN    64
#define HID     32
#define EMO     25
#define NHG     96              // H*G
#define EPW     28              // EMO padded to float4 multiple (16B rows)
#define BN_EPS  1e-5f
#define L1_EPS  1e-12f
#define NGRP    24              // 96 hg / 4 per group
#define GSPLIT  2               // grid.y: groups split across blocks
#define GPB     (NGRP / GSPLIT) // 12 groups per block
#define GW      (4 * HID * EPW)     // 3584 padded weights per group
#define GTOT    (GW + 4 * EPW)      // 3696 floats incl padded bias

// Scratch
__device__ float g_h2[BATCH * HID];              // pre-BN activations, 4 MB
__device__ float g_part[128 * 64];               // BN partials
__device__ float g_bn[64];                       // folded BN params
__device__ __align__(16) float g_wpack[NGRP * GTOT];  // packed weights, 354 KB

__device__ __forceinline__ float selu_f(float x) {
    const float LAM = 1.0507009873554805f;
    const float AL  = 1.6732632423543772f;
    return x > 0.f ? LAM * x : LAM * AL * (__expf(x) - 1.f);
}

// ---- packed fp32x2 (FFMA2) helpers ----
__device__ __forceinline__ unsigned long long pack2(float lo, float hi) {
    unsigned long long r;
    asm("mov.b64 %0, {%1, %2};" : "=l"(r) : "f"(lo), "f"(hi));
    return r;
}
__device__ __forceinline__ void unpack2(unsigned long long v, float& lo, float& hi) {
    asm("mov.b64 {%0, %1}, %2;" : "=f"(lo), "=f"(hi) : "l"(v));
}
__device__ __forceinline__ void fma2(unsigned long long& d,
                                     unsigned long long a, unsigned long long b) {
    asm("fma.rn.f32x2 %0, %1, %2, %3;" : "=l"(d) : "l"(a), "l"(b), "l"(d));
}

// ---- cp.async helpers ----
__device__ __forceinline__ void cp_async16(uint32_t smem, const void* gptr) {
    asm volatile("cp.async.ca.shared.global [%0], [%1], 16;"
                 :: "r"(smem), "l"(gptr) : "memory");
}
#define CP_COMMIT() asm volatile("cp.async.commit_group;" ::: "memory")
#define CP_WAIT0()  asm volatile("cp.async.wait_group 0;" ::: "memory")

// ---------------------------------------------------------------------------
// Kernel 0: pack Wh/bh into contiguous padded per-group blobs
// ---------------------------------------------------------------------------
__global__ void k_pack(const float* __restrict__ Wh, const float* __restrict__ bh)
{
    int g = blockIdx.x;          // 0..23
    int tid = threadIdx.x;
    for (int i = tid; i < GTOT; i += 256) {
        float v = 0.f;
        if (i < GW) {
            int hgl = i / (HID * EPW);
            int r   = i % (HID * EPW);
            int k = r / EPW, e = r % EPW;
            if (e < EMO)
                v = Wh[((size_t)(g * 4 + hgl) * HID + k) * EMO + e];
        } else {
            int r = i - GW;
            int hgl = r / EPW, e = r % EPW;
            if (e < EMO)
                v = bh[(size_t)(g * 4 + hgl) * EMO + e];
        }
        g_wpack[(size_t)g * GTOT + i] = v;
    }
}

// ---------------------------------------------------------------------------
// Kernel 1: h2 = selu(X@W1+b1)@W2 + b2      (one thread per batch row)
// ---------------------------------------------------------------------------
__global__ void __launch_bounds__(256) k_feat(
    const float* __restrict__ X,  const float* __restrict__ W1,
    const float* __restrict__ b1, const float* __restrict__ W2,
    const float* __restrict__ b2)
{
    __shared__ __align__(16) float w1s[F_IN * HID];
    __shared__ __align__(16) float w2s[HID * HID];
    __shared__ __align__(16) float b1s[HID];
    __shared__ __align__(16) float b2s[HID];

    int tid = threadIdx.x;
    for (int i = tid; i < F_IN * HID; i += 256) w1s[i] = W1[i];
    for (int i = tid; i < HID * HID; i += 256) w2s[i] = W2[i];
    if (tid < HID) { b1s[tid] = b1[tid]; b2s[tid] = b2[tid]; }
    __syncthreads();

    int row = blockIdx.x * 256 + tid;
    const float4* xg = reinterpret_cast<const float4*>(X + (size_t)row * F_IN);

    float4 h[8];
    const float4* b1v = reinterpret_cast<const float4*>(b1s);
#pragma unroll
    for (int j = 0; j < 8; j++) h[j] = b1v[j];

    const float4* w1v = reinterpret_cast<const float4*>(w1s);
#pragma unroll 4
    for (int i = 0; i < 16; i++) {
        float4 xv = xg[i];
#pragma unroll
        for (int c = 0; c < 4; c++) {
            float xi = (c == 0) ? xv.x : (c == 1) ? xv.y : (c == 2) ? xv.z : xv.w;
            int ii = i * 4 + c;
#pragma unroll
            for (int j = 0; j < 8; j++) {
                float4 w = w1v[ii * 8 + j];
                h[j].x = fmaf(xi, w.x, h[j].x);
                h[j].y = fmaf(xi, w.y, h[j].y);
                h[j].z = fmaf(xi, w.z, h[j].z);
                h[j].w = fmaf(xi, w.w, h[j].w);
            }
        }
    }
#pragma unroll
    for (int j = 0; j < 8; j++) {
        h[j].x = selu_f(h[j].x); h[j].y = selu_f(h[j].y);
        h[j].z = selu_f(h[j].z); h[j].w = selu_f(h[j].w);
    }

    float4 o[8];
    const float4* b2v = reinterpret_cast<const float4*>(b2s);
#pragma unroll
    for (int j = 0; j < 8; j++) o[j] = b2v[j];

    const float4* w2v = reinterpret_cast<const float4*>(w2s);
#pragma unroll
    for (int i = 0; i < 8; i++) {
#pragma unroll
        for (int c = 0; c < 4; c++) {
            float hi = (c == 0) ? h[i].x : (c == 1) ? h[i].y : (c == 2) ? h[i].z : h[i].w;
            int ii = i * 4 + c;
#pragma unroll
            for (int j = 0; j < 8; j++) {
                float4 w = w2v[ii * 8 + j];
                o[j].x = fmaf(hi, w.x, o[j].x);
                o[j].y = fmaf(hi, w.y, o[j].y);
                o[j].z = fmaf(hi, w.z, o[j].z);
                o[j].w = fmaf(hi, w.w, o[j].w);
            }
        }
    }
    float4* og = reinterpret_cast<float4*>(g_h2 + (size_t)row * HID);
#pragma unroll
    for (int j = 0; j < 8; j++) og[j] = o[j];
}

// ---------------------------------------------------------------------------
// Kernel 2: deterministic per-block partial sums of h2 and h2^2 per column
// ---------------------------------------------------------------------------
__global__ void __launch_bounds__(256) k_stats()
{
    __shared__ float ss1[256];
    __shared__ float ss2[256];
    int tid = threadIdx.x;
    int col = tid & 31;
    int grp = tid >> 5;
    int base = blockIdx.x * 256;

    float s1 = 0.f, s2 = 0.f;
    for (int r = grp; r < 256; r += 8) {
        float v = g_h2[(size_t)(base + r) * HID + col];
        s1 += v; s2 += v * v;
    }
    ss1[tid] = s1; ss2[tid] = s2;
    __syncthreads();
    if (tid < 32) {
        float a = 0.f, b = 0.f;
#pragma unroll
        for (int g = 0; g < 8; g++) { a += ss1[g * 32 + tid]; b += ss2[g * 32 + tid]; }
        g_part[blockIdx.x * 64 + tid]      = a;
        g_part[blockIdx.x * 64 + 32 + tid] = b;
    }
}

// ---------------------------------------------------------------------------
// Kernel 3: finalize BN params
// ---------------------------------------------------------------------------
__global__ void k_bn(const float* __restrict__ gamma, const float* __restrict__ beta)
{
    __shared__ float tot[64];
    int tid = threadIdx.x;
    float a = 0.f;
    for (int b = 0; b < 128; b++) a += g_part[b * 64 + tid];
    tot[tid] = a;
    __syncthreads();
    if (tid < 32) {
        float S = tot[tid], Q = tot[tid + 32];
        float mu  = S * (1.f / BATCH);
        float var = Q * (1.f / BATCH) - mu * mu;
        float rstd = rsqrtf(var + BN_EPS);
        float sc = gamma[tid] * rstd;
        g_bn[tid]      = sc;
        g_bn[32 + tid] = beta[tid] - mu * sc;
    }
}

// ---------------------------------------------------------------------------
// Kernel 4: heads GEMM + selu + L1 normalize.
// Grid (512, GSPLIT) x 128 threads: block = 64 rows x 12 groups (warp = hg).
// Thread: rows (lane, lane+32), 28 packed lanes (25 live) via FFMA2.
// Weights double-buffered in smem via cp.async from g_wpack; LDS.128 loads.
// Store staging double-buffered, overlaid on the dead compute weight buffer.
// ---------------------------------------------------------------------------
__global__ void __launch_bounds__(128, 5) k_heads(float* __restrict__ out)
{
    __shared__ __align__(16) float wbuf[2][GTOT];   // 2 x 14784 B
    __shared__ float es[64 * 33];                   // padded, conflict-free
    __shared__ float bns[64];

    int tid  = threadIdx.x;
    int warp = tid >> 5;     // 0..3 = hg within group (warp-uniform)
    int lane = tid & 31;     // rows lane, lane+32
    int grpBase = blockIdx.y * GPB;

    uint32_t ws0 = (uint32_t)__cvta_generic_to_shared(&wbuf[0][0]);
    uint32_t ws1 = (uint32_t)__cvta_generic_to_shared(&wbuf[1][0]);

    // prologue: async-prefetch first group (overlaps es fill)
    {
        const float4* s = reinterpret_cast<const float4*>(
            g_wpack + (size_t)grpBase * GTOT);
        for (int i = tid; i < GTOT / 4; i += 128)
            cp_async16(ws0 + i * 16, s + i);
    }
    CP_COMMIT();

    if (tid < 64) bns[tid] = g_bn[tid];
    __syncthreads();

    int rowBase = blockIdx.x * 64;
    {
        const float4* src = reinterpret_cast<const float4*>(g_h2 + (size_t)rowBase * HID);
        for (int i = tid; i < 512; i += 128) {
            float4 v = src[i];
            int row = i >> 3;
            int c   = (i & 7) * 4;
            es[row * 33 + c + 0] = selu_f(fmaf(v.x, bns[c + 0], bns[32 + c + 0]));
            es[row * 33 + c + 1] = selu_f(fmaf(v.y, bns[c + 1], bns[32 + c + 1]));
            es[row * 33 + c + 2] = selu_f(fmaf(v.z, bns[c + 2], bns[32 + c + 2]));
            es[row * 33 + c + 3] = selu_f(fmaf(v.w, bns[c + 3], bns[32 + c + 3]));
        }
    }

    for (int g = 0; g < GPB; g++) {
        int grp = grpBase + g;
        int b = g & 1;
        CP_WAIT0();
        __syncthreads();     // async weights visible to all; es ready (g==0)

        // prefetch next group into the other buffer (flies during compute)
        if (g + 1 < GPB) {
            const float4* s = reinterpret_cast<const float4*>(
                g_wpack + (size_t)(grp + 1) * GTOT);
            uint32_t d = b ? ws0 : ws1;
            for (int i = tid; i < GTOT / 4; i += 128)
                cp_async16(d + i * 16, s + i);
            CP_COMMIT();
        }

        float* wb = &wbuf[b][0];
        unsigned long long A0[14], A1[14];
        {
            const unsigned long long* bp =
                reinterpret_cast<const unsigned long long*>(wb + GW + warp * EPW);
#pragma unroll
            for (int j = 0; j < 14; j++) { A0[j] = bp[j]; A1[j] = bp[j]; }
        }

        const float4* wr0 = reinterpret_cast<const float4*>(wb + warp * HID * EPW);
#pragma unroll 2
        for (int k = 0; k < HID; k++) {
            unsigned long long E0 = pack2(es[lane * 33 + k],        es[lane * 33 + k]);
            unsigned long long E1 = pack2(es[(lane + 32) * 33 + k], es[(lane + 32) * 33 + k]);
            const float4* wr = wr0 + k * 7;
#pragma unroll
            for (int j = 0; j < 7; j++) {
                union { float4 f; unsigned long long u[2]; } w4;
                w4.f = wr[j];
                fma2(A0[2 * j],     E0, w4.u[0]);
                fma2(A0[2 * j + 1], E0, w4.u[1]);
                fma2(A1[2 * j],     E1, w4.u[0]);
                fma2(A1[2 * j + 1], E1, w4.u[1]);
            }
        }

        // selu + L1 sums, in place (lanes 25..27 dead)
        float s0 = 0.f, s1 = 0.f, a0t, a1t;
#pragma unroll
        for (int j = 0; j < 12; j++) {
            float lo, hi;
            unpack2(A0[j], lo, hi);
            lo = selu_f(lo); hi = selu_f(hi);
            s0 += fabsf(lo) + fabsf(hi);
            A0[j] = pack2(lo, hi);
            unpack2(A1[j], lo, hi);
            lo = selu_f(lo); hi = selu_f(hi);
            s1 += fabsf(lo) + fabsf(hi);
            A1[j] = pack2(lo, hi);
        }
        {
            float lo, hi;
            unpack2(A0[12], lo, hi); a0t = selu_f(lo); s0 += fabsf(a0t);
            unpack2(A1[12], lo, hi); a1t = selu_f(lo); s1 += fabsf(a1t);
        }
        float inv0 = 1.f / fmaxf(s0, L1_EPS);
        float inv1 = 1.f / fmaxf(s1, L1_EPS);

        __syncthreads();     // all warps done reading wbuf[b]

        // double-buffered store staging overlaid on the dead compute buffer
        float* stg0 = wb;             // [0, 1600)
        float* stg1 = wb + 1664;      // [1664, 3264) < GTOT
        auto writeStage = [&](float* stg) {
#pragma unroll
            for (int j = 0; j < 12; j++) {
                float lo, hi;
                unpack2(A0[j], lo, hi);
                stg[lane * EMO + 2 * j]     = lo * inv0;
                stg[lane * EMO + 2 * j + 1] = hi * inv0;
                unpack2(A1[j], lo, hi);
                stg[(lane + 32) * EMO + 2 * j]     = lo * inv1;
                stg[(lane + 32) * EMO + 2 * j + 1] = hi * inv1;
            }
            stg[lane * EMO + 24]        = a0t * inv0;
            stg[(lane + 32) * EMO + 24] = a1t * inv1;
        };

        if (warp == 0) writeStage(stg0);
        __syncthreads();
#pragma unroll
        for (int s = 0; s < 4; s++) {
            float* cur = (s & 1) ? stg1 : stg0;
            if (s < 3 && warp == s + 1) writeStage((s & 1) ? stg0 : stg1);
            if (lane < EMO) {
                float* ob = out + (size_t)rowBase * (NHG * EMO)
                                + (size_t)(grp * 4 + s) * EMO;
                int r0 = warp * 16;
#pragma unroll
                for (int rr = 0; rr < 16; rr++)
                    __stcs(&ob[(size_t)(r0 + rr) * (NHG * EMO) + lane],
                           cur[(r0 + rr) * EMO + lane]);
            }
            __syncthreads();
        }
    }
}

// ---------------------------------------------------------------------------
extern "C" void kernel_launch(void* const* d_in, const int* in_sizes, int n_in,
                              void* d_out, int out_size)
{
    const float* X     = (const float*)d_in[0];
    const float* W1    = (const float*)d_in[1];
    const float* b1    = (const float*)d_in[2];
    const float* W2    = (const float*)d_in[3];
    const float* b2    = (const float*)d_in[4];
    const float* gamma = (const float*)d_in[5];
    const float* beta  = (const float*)d_in[6];
    const float* Wh    = (const float*)d_in[7];
    const float* bh    = (const float*)d_in[8];
    float* out = (float*)d_out;

    k_pack <<<NGRP, 256>>>(Wh, bh);
    k_feat <<<BATCH / 256, 256>>>(X, W1, b1, W2, b2);
    k_stats<<<128, 256>>>();
    k_bn   <<<1, 64>>>(gamma, beta);
    dim3 hg(BATCH / 64, GSPLIT);
    k_heads<<<hg, 128>>>(out);
}